// round 13
// baseline (speedup 1.0000x reference)
#include <cuda_runtime.h>
#include <cuda_fp16.h>
#include <math.h>
#include <stdint.h>

#define BQ 32
#define BP 256
#define NB 288
#define L 16
#define LP 20          // padded token length (2 zeros each side)
#define CIN 8192
#define H1 256
#define H2 32
#define NW (CIN/32)
#define KTOT 1280      // conv GEMM K = 5*256
#define NCHK 10        // K chunks of 128

// ================= scratch (device globals) =================
__device__ float    g_encT[CIN*H1];
__device__ __half   g_wH[3*H1*KTOT];   // per layer: chunk128-major [c][o][128]
__device__ float    g_w1T[2*H1*H2];
__device__ float    g_w2T[H2*H2];
__device__ float    g_xe[NB*L*H1];
__device__ __half   g_hAH[NB*LP*H1];   // activations, fp16 (padded)
__device__ __half   g_hBH[NB*LP*H1];
__device__ float    g_out3[NB*L*H1];
__device__ unsigned g_mask[NB*NW];
__device__ float    g_emb[NB*H1];
__device__ float    g_desc[BQ*BP];

// ================= prep kernels (3 separate launches) =================
__global__ void k_prepA(const float* __restrict__ dw1, const float* __restrict__ dw2) {
    int i = blockIdx.x * 256 + threadIdx.x;   // grid 2880
    if (i < NB * NW) g_mask[i] = 0u;
    ((unsigned*)g_hAH)[i] = 0u;
    ((unsigned*)g_hBH)[i] = 0u;
    if (i < 512 * 32) { int r = i >> 5, j = i & 31; g_w1T[i] = dw1[j * 512 + r]; }
    if (i < 32 * 32)  { int m = i >> 5, j = i & 31; g_w2T[i] = dw2[j * 32 + m]; }
}

// conv weights (O,I,5) fp32 -> fp16, chunk128-major [c][o][128], k = dl*256+i
__global__ void k_prepB(const float* __restrict__ cw1, const float* __restrict__ cw2,
                        const float* __restrict__ cw3) {
    int idx = blockIdx.x * 256 + threadIdx.x;   // grid 3840
    int layer = idx / (H1 * KTOT);
    int r = idx - layer * (H1 * KTOT);
    int o = r / KTOT, k = r - o * KTOT;
    int dl = k >> 8, i = k & 255;
    const float* src = (layer == 0) ? cw1 : (layer == 1) ? cw2 : cw3;
    float v = src[o * 1280 + i * 5 + dl];
    int c = k >> 7, w = k & 127;   // chunk128-major
    size_t dst = (size_t)layer * (H1 * KTOT) + (size_t)c * (H1 * 128) + o * 128 + w;
    g_wH[dst] = __float2half_rn(v);
}

// enc_w [H1][CIN] -> encT [CIN][H1]
__global__ void k_prepC(const float* __restrict__ enc_w) {
    __shared__ float tile[32][33];
    int cb = blockIdx.x;   // grid 2048
    int c0 = (cb & 255) * 32, r0 = (cb >> 8) * 32;
    int tid = threadIdx.x;
    int tx = tid & 31, ty = tid >> 5;
    int c = c0 + tx;
#pragma unroll
    for (int dr = ty; dr < 32; dr += 8)
        tile[dr][tx] = enc_w[(size_t)(r0 + dr) * CIN + c];
    __syncthreads();
    int r = r0 + tx;
#pragma unroll
    for (int dc = ty; dc < 32; dc += 8)
        g_encT[(size_t)(c0 + dc) * H1 + r] = tile[tx][dc];
}

// ================= encode + bloom (warp-scan compaction) =================
#define NZCAP 2048
__global__ void k_encode(const float* __restrict__ qx, const float* __restrict__ px) {
    __shared__ unsigned short sidx[NZCAP];
    __shared__ int wsum[8];
    int r = blockIdx.x, l = blockIdx.y, t = threadIdx.x;
    int lane = t & 31, w = t >> 5;
    const float* x = (r < BQ) ? (qx + (size_t)(r * L + l) * CIN)
                              : (px + (size_t)((r - BQ) * L + l) * CIN);
    const float4* x4 = (const float4*)(x + t * 32);
    int cnt = 0;
    unsigned mword = 0;
#pragma unroll
    for (int j = 0; j < 8; j++) {
        float4 v = x4[j];
        if (v.x != 0.f) { cnt++; mword |= 1u << (j * 4 + 0); }
        if (v.y != 0.f) { cnt++; mword |= 1u << (j * 4 + 1); }
        if (v.z != 0.f) { cnt++; mword |= 1u << (j * 4 + 2); }
        if (v.w != 0.f) { cnt++; mword |= 1u << (j * 4 + 3); }
    }
    if (mword) atomicOr(&g_mask[r * NW + t], mword);
    int pref = cnt;
#pragma unroll
    for (int d = 1; d < 32; d <<= 1) {
        int v = __shfl_up_sync(0xffffffffu, pref, d);
        if (lane >= d) pref += v;
    }
    if (lane == 31) wsum[w] = pref;
    __syncthreads();
    int wbase = 0, total = 0;
#pragma unroll
    for (int k = 0; k < 8; k++) {
        int v = wsum[k];
        if (k < w) wbase += v;
        total += v;
    }
    if (total > NZCAP) total = NZCAP;
    int base = wbase + pref - cnt;
    unsigned m = mword;
    while (m && base < NZCAP) {
        int b = __ffs(m) - 1;
        m &= m - 1;
        sidx[base++] = (unsigned short)(t * 32 + b);
    }
    __syncthreads();
    float a0 = 0.f, a1 = 0.f, a2 = 0.f, a3 = 0.f;
    int j = 0;
    for (; j + 4 <= total; j += 4) {
        a0 += g_encT[(int)sidx[j + 0] * H1 + t];
        a1 += g_encT[(int)sidx[j + 1] * H1 + t];
        a2 += g_encT[(int)sidx[j + 2] * H1 + t];
        a3 += g_encT[(int)sidx[j + 3] * H1 + t];
    }
    for (; j < total; j++) a0 += g_encT[(int)sidx[j] * H1 + t];
    float acc = (a0 + a1) + (a2 + a3);
    g_xe[(size_t)(r * L + l) * H1 + t] = acc;
    g_hAH[((size_t)r * LP + (l + 2)) * H1 + t] = __float2half_rn(acc);
}

// ================= conv via mma.sync pure fp16 GEMM =================
// C = Ah*Wh (fp32 accum). CTA: 512 threads (16 warps = 4M x 4N),
// tile M=64 x N=128, warp tile 16x32. K=1280 in 10 chunks of 128;
// 3-stage cp.async ring, ONE sync per chunk. 4 independent MMA chains/kk.
// Row pitch 136 halves (272B) -> ldmatrix conflict-free (8x16B covers banks).
#define PITCH 136
#define STG   (192*PITCH)   // halves per stage: A 64 rows + B 128 rows
#define BHOF  (64*PITCH)    // 8704
#define NSTAGE 3
#define CONV_SMEM (NSTAGE*STG*2 + 512)

#define CP_ASYNC16(sa, gp) asm volatile("cp.async.cg.shared.global [%0], [%1], 16;" :: "r"(sa), "l"(gp))
#define CP_COMMIT()        asm volatile("cp.async.commit_group;")
#define CP_WAIT(n)         asm volatile("cp.async.wait_group %0;" :: "n"(n))
#define LDMX4(r0, r1, r2, r3, addr) \
    asm volatile("ldmatrix.sync.aligned.m8n8.x4.shared.b16 {%0,%1,%2,%3}, [%4];" \
        : "=r"(r0), "=r"(r1), "=r"(r2), "=r"(r3) : "r"(addr))

__device__ __forceinline__ uint32_t smem_u32(const void* p) {
    uint32_t a;
    asm("{ .reg .u64 t; cvta.to.shared.u64 t, %1; cvt.u32.u64 %0, t; }" : "=r"(a) : "l"(p));
    return a;
}

__device__ __forceinline__ void mma16816(float* c, const unsigned* a,
                                         unsigned b0, unsigned b1) {
    asm volatile(
        "mma.sync.aligned.m16n8k16.row.col.f32.f16.f16.f32 "
        "{%0,%1,%2,%3}, {%4,%5,%6,%7}, {%8,%9}, {%0,%1,%2,%3};"
        : "+f"(c[0]), "+f"(c[1]), "+f"(c[2]), "+f"(c[3])
        : "r"(a[0]), "r"(a[1]), "r"(a[2]), "r"(a[3]), "r"(b0), "r"(b1));
}

__global__ void __launch_bounds__(512) k_conv_mma(
    const __half* __restrict__ inH,
    const __half* __restrict__ wH,
    const float* __restrict__ bias,
    __half* __restrict__ outH,
    float* __restrict__ outF) {
    extern __shared__ __half sm[];
    float* sbias = (float*)(sm + NSTAGE * STG);
    uint32_t su = smem_u32(sm);
    int tid = threadIdx.x;
    int wid = tid >> 5, lane = tid & 31;
    int wm = wid >> 2, wn = wid & 3;
    int g = lane >> 2, tg = lane & 3;
    int R0 = blockIdx.x * 64;
    int N0 = blockIdx.y * 128;

    if (tid < 128) sbias[tid] = bias[N0 + tid];

    // staging: A 64 rows x 16 segs (2 cp/thread); B 128 rows x 16 segs (4 cp/thread)
    int ar = tid >> 3, as = tid & 7;
    int br = tid >> 2, bs = tid & 3;
    int grow = R0 + ar;
    int gs = grow >> 4, gl = grow & 15;

    auto stage_issue = [&](int c) {
        int st = c - (c / 3) * 3;
        uint32_t sb = su + st * (STG * 2);
        int dl = c >> 1, i0 = (c & 1) * 128;
        size_t ga = ((size_t)gs * LP + gl + dl) * H1 + i0;
#pragma unroll
        for (int j = 0; j < 2; j++) {
            int seg = as + j * 8;
            CP_ASYNC16(sb + (ar * PITCH + seg * 8) * 2, inH + ga + seg * 8);
        }
        size_t gb = (size_t)c * (H1 * 128) + ((size_t)N0 + br) * 128;
#pragma unroll
        for (int j = 0; j < 4; j++) {
            int seg = bs + j * 4;
            CP_ASYNC16(sb + (BHOF + br * PITCH + seg * 8) * 2, wH + gb + seg * 8);
        }
    };

    // ldmatrix lane-address components
    int lrow = lane & 7, lm = lane >> 3;
    int aRowOff = lrow + (lm & 1) * 8;
    int aColOff = (lm >> 1) * 8;
    int bRowOff = (lm >> 1) * 8 + lrow;
    int bColOff = (lm & 1) * 8;

    float C[4][4];
#pragma unroll
    for (int nt = 0; nt < 4; nt++)
#pragma unroll
        for (int j = 0; j < 4; j++) C[nt][j] = 0.f;

    stage_issue(0); CP_COMMIT();
    stage_issue(1); CP_COMMIT();

    for (int c = 0; c < NCHK; c++) {
        if (c == NCHK - 1) { CP_WAIT(0); } else { CP_WAIT(1); }
        __syncthreads();   // all warps done with chunk c-1 -> its slot is free
        if (c + 2 < NCHK) { stage_issue(c + 2); CP_COMMIT(); }
        uint32_t base = su + (c - (c / 3) * 3) * (STG * 2);
#pragma unroll
        for (int kk = 0; kk < 8; kk++) {
            unsigned ah[4];
            uint32_t ad = base + ((wm * 16 + aRowOff) * PITCH + kk * 16 + aColOff) * 2;
            LDMX4(ah[0], ah[1], ah[2], ah[3], ad);
            unsigned bh[4][2];
#pragma unroll
            for (int ntp = 0; ntp < 2; ntp++) {
                uint32_t bd = base + (BHOF + (wn * 32 + ntp * 16 + bRowOff) * PITCH + kk * 16 + bColOff) * 2;
                LDMX4(bh[2*ntp][0], bh[2*ntp][1], bh[2*ntp+1][0], bh[2*ntp+1][1], bd);
            }
            // 4 independent depth-1 MMA chains
#pragma unroll
            for (int nt = 0; nt < 4; nt++)
                mma16816(C[nt], ah, bh[nt][0], bh[nt][1]);
        }
    }

    // epilogue: bias + relu; write fp16 (padded) or fp32 (last layer)
    int row0 = R0 + wm * 16 + g;
#pragma unroll
    for (int nt = 0; nt < 4; nt++) {
        int lc = wn * 32 + nt * 8 + tg * 2;
        int col = N0 + lc;
        float b0v = sbias[lc], b1v = sbias[lc + 1];
        float v00 = fmaxf(C[nt][0] + b0v, 0.f);
        float v01 = fmaxf(C[nt][1] + b1v, 0.f);
        float v10 = fmaxf(C[nt][2] + b0v, 0.f);
        float v11 = fmaxf(C[nt][3] + b1v, 0.f);
        int s0 = row0 >> 4, l0 = row0 & 15;
        int s1 = (row0 + 8) >> 4, l1 = (row0 + 8) & 15;
        if (outF) {
            *(float2*)(outF + ((size_t)s0 * L + l0) * H1 + col) = make_float2(v00, v01);
            *(float2*)(outF + ((size_t)s1 * L + l1) * H1 + col) = make_float2(v10, v11);
        } else {
            size_t o0 = ((size_t)s0 * LP + l0 + 2) * H1 + col;
            size_t o1 = ((size_t)s1 * LP + l1 + 2) * H1 + col;
            *(__half2*)(outH + o0) = __halves2half2(__float2half_rn(v00), __float2half_rn(v01));
            *(__half2*)(outH + o1) = __halves2half2(__float2half_rn(v10), __float2half_rn(v11));
        }
    }
}

// ================= mean over tokens (+ residual) =================
__global__ void k_emb() {
    int r = blockIdx.x, f = threadIdx.x;
    float acc = 0.f;
#pragma unroll
    for (int l = 0; l < 16; l++)
        acc += g_out3[(size_t)(r * L + l) * H1 + f] + g_xe[(size_t)(r * L + l) * H1 + f];
    g_emb[r * H1 + f] = acc * (1.f / 16.f);
}

// ===== fused tail: qbits + pairwise MLP + sparse desc_sim, per (q, 8 p's) =====
__global__ void k_fused(const float* __restrict__ b1, const float* __restrict__ b2,
                        const float* __restrict__ w3) {
    __shared__ unsigned qm[NW];
    __shared__ float sqe[H1];
    __shared__ float red[8];
    int q = blockIdx.y, pg = blockIdx.x;
    int t = threadIdx.x, lane = t & 31, wid = t >> 5;
    unsigned qw = g_mask[q * NW + t];
    qm[t] = qw;
    sqe[t] = fmaxf(g_emb[q * H1 + t], 0.f);
    int pc = __popc(qw);
#pragma unroll
    for (int off = 16; off; off >>= 1) pc += __shfl_down_sync(0xffffffffu, pc, off);
    if (lane == 0) red[wid] = (float)pc;
    __syncthreads();
    float qbits = 0.f;
#pragma unroll
    for (int k = 0; k < 8; k++) qbits += red[k];

    int p = pg * 8 + wid;
    const float* pe = g_emb + (size_t)(BQ + p) * H1;
    int j = lane;
    float acc = b1[j];
#pragma unroll 4
    for (int i = 0; i < 256; i++) acc += sqe[i] * g_w1T[i * 32 + j];
#pragma unroll 4
    for (int i = 0; i < 256; i++) acc += fmaxf(pe[i], 0.f) * g_w1T[(256 + i) * 32 + j];
    float h2v = fmaxf(acc, 0.f);
    float acc3 = b2[j];
#pragma unroll
    for (int m = 0; m < 32; m++)
        acc3 += __shfl_sync(0xffffffffu, h2v, m) * g_w2T[m * 32 + j];
    float h3v = fmaxf(acc3, 0.f);
    float hj[32];
#pragma unroll
    for (int m = 0; m < 32; m++) hj[m] = __shfl_sync(0xffffffffu, h3v, m);

    const unsigned* pm = g_mask + (size_t)(BQ + p) * NW;
    float s = 0.f;
    int cnt = 0;
    for (int w8 = 0; w8 < 8; w8++) {
        int wi = w8 * 32 + lane;
        unsigned m = qm[wi] & pm[wi];
        cnt += __popc(m);
        while (m) {
            int b = __ffs(m) - 1;
            m &= m - 1;
            int c = wi * 32 + b;
            const float4* r4 = (const float4*)(w3 + (size_t)c * 32);
            float wv = 0.f;
#pragma unroll
            for (int j4 = 0; j4 < 8; j4++) {
                float4 v = r4[j4];
                wv += hj[j4*4] * v.x + hj[j4*4+1] * v.y + hj[j4*4+2] * v.z + hj[j4*4+3] * v.w;
            }
            s += (wv >= 0.f) ? wv : wv * 0.125f;
        }
    }
#pragma unroll
    for (int off = 16; off; off >>= 1) {
        s += __shfl_down_sync(0xffffffffu, s, off);
        cnt += __shfl_down_sync(0xffffffffu, cnt, off);
    }
    if (lane == 0) g_desc[q * 256 + p] = ((float)cnt + s) / qbits;
}

// ================= normalization + geo fusion =================
__global__ void k_final(const float* __restrict__ qloc, const float* __restrict__ ploc,
                        const float* __restrict__ pa, const float* __restrict__ pb,
                        const float* __restrict__ pc, const float* __restrict__ pd,
                        float* __restrict__ out) {
    __shared__ float red[256];
    int q = blockIdx.x, p = threadIdx.x;
    float ds = g_desc[q * 256 + p];
    red[p] = ds;
    __syncthreads();
    for (int s = 128; s > 0; s >>= 1) {
        if (p < s) red[p] += red[p + s];
        __syncthreads();
    }
    float mean = red[0] / 256.f;
    __syncthreads();
    float df = ds - mean;
    red[p] = df * df;
    __syncthreads();
    for (int s = 128; s > 0; s >>= 1) {
        if (p < s) red[p] += red[p + s];
        __syncthreads();
    }
    float stddev = sqrtf(red[0] / 255.f);
    float dsn = df / (stddev + 1e-6f);
    float dx = qloc[q * 2] - ploc[p * 2];
    float dy = qloc[q * 2 + 1] - ploc[p * 2 + 1];
    float dist = sqrtf(dx * dx + dy * dy);
    float A = *pa, B = *pb, Cc2 = *pc, D = *pd;
    float sig = 1.f / (1.f + expf(-(A * dsn + B)));
    out[q * 256 + p] = (Cc2 - sig) * (-logf(dist + 1.f) - D);
}

// ================= launch =================
extern "C" void kernel_launch(void* const* d_in, const int* in_sizes, int n_in,
                              void* d_out, int out_size) {
    const float* query_x  = (const float*)d_in[0];
    const float* query_loc = (const float*)d_in[1];
    const float* poi_x    = (const float*)d_in[2];
    const float* poi_loc  = (const float*)d_in[3];
    const float* enc_w    = (const float*)d_in[4];
    const float* cw1 = (const float*)d_in[5];  const float* cb1 = (const float*)d_in[6];
    const float* cw2 = (const float*)d_in[7];  const float* cb2 = (const float*)d_in[8];
    const float* cw3 = (const float*)d_in[9];  const float* cb3 = (const float*)d_in[10];
    const float* dw1 = (const float*)d_in[11]; const float* db1 = (const float*)d_in[12];
    const float* dw2 = (const float*)d_in[13]; const float* db2 = (const float*)d_in[14];
    const float* dw3 = (const float*)d_in[15];
    const float* pa = (const float*)d_in[16];
    const float* pb = (const float*)d_in[17];
    const float* pc = (const float*)d_in[18];
    const float* pd = (const float*)d_in[19];
    float* out = (float*)d_out;

    float *p_out3;
    __half *p_wH, *p_hAH, *p_hBH;
    cudaGetSymbolAddress((void**)&p_wH, g_wH);
    cudaGetSymbolAddress((void**)&p_hAH, g_hAH);
    cudaGetSymbolAddress((void**)&p_hBH, g_hBH);
    cudaGetSymbolAddress((void**)&p_out3, g_out3);

    cudaFuncSetAttribute(k_conv_mma, cudaFuncAttributeMaxDynamicSharedMemorySize, CONV_SMEM);

    // prep (3 launches so encode is launch #4 for the profiler)
    k_prepA<<<2880, 256>>>(dw1, dw2);
    k_prepB<<<3840, 256>>>(cw1, cw2, cw3);
    k_prepC<<<2048, 256>>>(enc_w);
    // encode + blooms (launch #4)
    k_encode<<<dim3(NB, L), 256>>>(query_x, poi_x);
    // conv stack: pure fp16 (Ah*Wh), 512-thr CTAs, K128 chunks, 3-stage ring
    dim3 cgrid(NB * L / 64, 2);
    k_conv_mma<<<cgrid, 512, CONV_SMEM>>>(p_hAH, p_wH, cb1, p_hBH, (float*)0);
    k_conv_mma<<<cgrid, 512, CONV_SMEM>>>(p_hBH, p_wH + H1 * KTOT, cb2, p_hAH, (float*)0);
    k_conv_mma<<<cgrid, 512, CONV_SMEM>>>(p_hAH, p_wH + 2 * H1 * KTOT, cb3, (__half*)0, p_out3);
    // tail
    k_emb<<<NB, 256>>>();
    k_fused<<<dim3(32, 32), 256>>>(db1, db2, dw3);
    k_final<<<BQ, 256>>>(query_loc, poi_loc, pa, pb, pc, pd, out);
}

// round 14
// speedup vs baseline: 1.1131x; 1.1131x over previous
#include <cuda_runtime.h>
#include <cuda_fp16.h>
#include <math.h>
#include <stdint.h>

#define BQ 32
#define BP 256
#define NB 288
#define L 16
#define LP 20          // padded token length (2 zeros each side)
#define CIN 8192
#define H1 256
#define H2 32
#define NW (CIN/32)
#define KTOT 1280      // conv GEMM K = 5*256
#define NCHK 20        // K chunks of 64

// ================= scratch (device globals) =================
__device__ float    g_encT[CIN*H1];
__device__ __half   g_wH[3*H1*KTOT];   // per layer: chunk64-major [c][o][64]
__device__ float    g_w1T[2*H1*H2];
__device__ float    g_w2T[H2*H2];
__device__ float    g_xe[NB*L*H1];
__device__ __half   g_hAH[NB*LP*H1];   // activations, fp16 (padded)
__device__ __half   g_hBH[NB*LP*H1];
__device__ float    g_out3[NB*L*H1];
__device__ unsigned g_mask[NB*NW];
__device__ float    g_emb[NB*H1];
__device__ float    g_desc[BQ*BP];

// ================= fused prep (3 zones) =================
#define ZA 2880
#define ZB 3840
#define ZC 2048
__global__ void k_prep(const float* __restrict__ dw1, const float* __restrict__ dw2,
                       const float* __restrict__ cw1, const float* __restrict__ cw2,
                       const float* __restrict__ cw3, const float* __restrict__ enc_w) {
    __shared__ float tile[32][33];
    int bb = blockIdx.x, tid = threadIdx.x;
    if (bb < ZA) {
        int i = bb * 256 + tid;
        if (i < NB * NW) g_mask[i] = 0u;
        ((unsigned*)g_hAH)[i] = 0u;
        ((unsigned*)g_hBH)[i] = 0u;
        if (i < 512 * 32) { int r = i >> 5, j = i & 31; g_w1T[i] = dw1[j * 512 + r]; }
        if (i < 32 * 32)  { int m = i >> 5, j = i & 31; g_w2T[i] = dw2[j * 32 + m]; }
    } else if (bb < ZA + ZB) {
        int idx = (bb - ZA) * 256 + tid;
        int layer = idx / (H1 * KTOT);
        int r = idx - layer * (H1 * KTOT);
        int o = r / KTOT, k = r - o * KTOT;
        int dl = k >> 8, i = k & 255;
        const float* src = (layer == 0) ? cw1 : (layer == 1) ? cw2 : cw3;
        float v = src[o * 1280 + i * 5 + dl];
        int c = k >> 6, w = k & 63;   // chunk64-major
        size_t dst = (size_t)layer * (H1 * KTOT) + (size_t)c * (H1 * 64) + o * 64 + w;
        g_wH[dst] = __float2half_rn(v);
    } else {
        int cb = bb - ZA - ZB;
        int c0 = (cb & 255) * 32, r0 = (cb >> 8) * 32;
        int tx = tid & 31, ty = tid >> 5;
        int c = c0 + tx;
#pragma unroll
        for (int dr = ty; dr < 32; dr += 8)
            tile[dr][tx] = enc_w[(size_t)(r0 + dr) * CIN + c];
        __syncthreads();
        int r = r0 + tx;
#pragma unroll
        for (int dc = ty; dc < 32; dc += 8)
            g_encT[(size_t)(c0 + dc) * H1 + r] = tile[tx][dc];
    }
}

// ======= encode + bloom: COALESCED x reads (block-strided float4) =======
// Thread t, iter j reads float4 at float offset j*1024 + 4t (warp-contiguous),
// owning channels j*1024+4t .. +3. Nonzero nibbles packed into one u32.
// Bloom bits via smem atomicOr (order-independent); warp-scan compaction.
#define NZCAP 2048
__global__ void k_encode(const float* __restrict__ qx, const float* __restrict__ px) {
    __shared__ unsigned short sidx[NZCAP];
    __shared__ int wsum[8];
    __shared__ unsigned smask[256];
    int r = blockIdx.x, l = blockIdx.y, t = threadIdx.x;
    int lane = t & 31, w = t >> 5;
    const float* x = (r < BQ) ? (qx + (size_t)(r * L + l) * CIN)
                              : (px + (size_t)((r - BQ) * L + l) * CIN);
    smask[t] = 0u;
    __syncthreads();
    const float4* x4 = (const float4*)x;
    unsigned nib = 0;
#pragma unroll
    for (int j = 0; j < 8; j++) {
        float4 v = x4[j * 256 + t];   // coalesced: lane-contiguous 16B
        unsigned b = 0;
        if (v.x != 0.f) b |= 1u;
        if (v.y != 0.f) b |= 2u;
        if (v.z != 0.f) b |= 4u;
        if (v.w != 0.f) b |= 8u;
        nib |= b << (j * 4);
        if (b) atomicOr(&smask[j * 32 + (t >> 3)], b << ((t & 7) * 4));
    }
    int cnt = __popc(nib);
    // warp-level inclusive prefix of cnt
    int pref = cnt;
#pragma unroll
    for (int d = 1; d < 32; d <<= 1) {
        int v = __shfl_up_sync(0xffffffffu, pref, d);
        if (lane >= d) pref += v;
    }
    if (lane == 31) wsum[w] = pref;
    __syncthreads();
    int wbase = 0, total = 0;
#pragma unroll
    for (int k = 0; k < 8; k++) {
        int v = wsum[k];
        if (k < w) wbase += v;
        total += v;
    }
    if (total > NZCAP) total = NZCAP;
    int base = wbase + pref - cnt;
    unsigned m = nib;
    while (m && base < NZCAP) {
        int bpos = __ffs(m) - 1;
        m &= m - 1;
        int j = bpos >> 2, k = bpos & 3;
        sidx[base++] = (unsigned short)(j * 1024 + t * 4 + k);
    }
    // bloom bits to global (g_mask accumulates over 16 l-blocks)
    __syncthreads();
    unsigned mw = smask[t];
    if (mw) atomicOr(&g_mask[r * NW + t], mw);
    // gather-accumulate with 4 independent accumulators (coalesced rows)
    float a0 = 0.f, a1 = 0.f, a2 = 0.f, a3 = 0.f;
    int j = 0;
    for (; j + 4 <= total; j += 4) {
        a0 += g_encT[(int)sidx[j + 0] * H1 + t];
        a1 += g_encT[(int)sidx[j + 1] * H1 + t];
        a2 += g_encT[(int)sidx[j + 2] * H1 + t];
        a3 += g_encT[(int)sidx[j + 3] * H1 + t];
    }
    for (; j < total; j++) a0 += g_encT[(int)sidx[j] * H1 + t];
    float acc = (a0 + a1) + (a2 + a3);
    g_xe[(size_t)(r * L + l) * H1 + t] = acc;
    g_hAH[((size_t)r * LP + (l + 2)) * H1 + t] = __float2half_rn(acc);
}

// ================= conv via mma.sync pure fp16 GEMM (R12-exact) =================
// C = Ah*Wh (fp32 accum). CTA: 512 threads (16 warps = 4M x 4N),
// tile M=64 x N=128, warp tile 16x32. K=1280 in 20 chunks of 64;
// 3-stage cp.async ring, ONE sync per chunk. 4 independent MMA chains/kk.
// Row pitch 72 halves (144B) -> ldmatrix conflict-free. 2 CTAs/SM.
#define STG   13824   // halves per stage: AH 4608 | BH 9216
#define BHOF  4608
#define NSTAGE 3
#define CONV_SMEM (NSTAGE*STG*2 + 512)

#define CP_ASYNC16(sa, gp) asm volatile("cp.async.cg.shared.global [%0], [%1], 16;" :: "r"(sa), "l"(gp))
#define CP_COMMIT()        asm volatile("cp.async.commit_group;")
#define CP_WAIT(n)         asm volatile("cp.async.wait_group %0;" :: "n"(n))
#define LDMX4(r0, r1, r2, r3, addr) \
    asm volatile("ldmatrix.sync.aligned.m8n8.x4.shared.b16 {%0,%1,%2,%3}, [%4];" \
        : "=r"(r0), "=r"(r1), "=r"(r2), "=r"(r3) : "r"(addr))

__device__ __forceinline__ uint32_t smem_u32(const void* p) {
    uint32_t a;
    asm("{ .reg .u64 t; cvta.to.shared.u64 t, %1; cvt.u32.u64 %0, t; }" : "=r"(a) : "l"(p));
    return a;
}

__device__ __forceinline__ void mma16816(float* c, const unsigned* a,
                                         unsigned b0, unsigned b1) {
    asm volatile(
        "mma.sync.aligned.m16n8k16.row.col.f32.f16.f16.f32 "
        "{%0,%1,%2,%3}, {%4,%5,%6,%7}, {%8,%9}, {%0,%1,%2,%3};"
        : "+f"(c[0]), "+f"(c[1]), "+f"(c[2]), "+f"(c[3])
        : "r"(a[0]), "r"(a[1]), "r"(a[2]), "r"(a[3]), "r"(b0), "r"(b1));
}

__global__ void __launch_bounds__(512) k_conv_mma(
    const __half* __restrict__ inH,
    const __half* __restrict__ wH,
    const float* __restrict__ bias,
    __half* __restrict__ outH,
    float* __restrict__ outF) {
    extern __shared__ __half sm[];
    float* sbias = (float*)(sm + NSTAGE * STG);
    uint32_t su = smem_u32(sm);
    int tid = threadIdx.x;
    int wid = tid >> 5, lane = tid & 31;
    int wm = wid >> 2, wn = wid & 3;
    int g = lane >> 2, tg = lane & 3;
    int R0 = blockIdx.x * 64;
    int N0 = blockIdx.y * 128;

    if (tid < 128) sbias[tid] = bias[N0 + tid];

    // staging: A 64 rows x 8 segs (1 cp/thread); B 128 rows x 8 segs (2/thread)
    int ar = tid >> 3, as = tid & 7;
    int grow = R0 + ar;
    int gs = grow >> 4, gl = grow & 15;

    auto stage_issue = [&](int c) {
        int st = c - (c / 3) * 3;
        uint32_t sb = su + st * (STG * 2);
        int dl = c >> 2, i0 = (c & 3) * 64;
        size_t ga = ((size_t)gs * LP + gl + dl) * H1 + i0 + as * 8;
        CP_ASYNC16(sb + (ar * 72 + as * 8) * 2, inH + ga);
        size_t gw = (size_t)c * (H1 * 64);
#pragma unroll
        for (int hh = 0; hh < 2; hh++) {
            int row = hh * 64 + ar;
            size_t gb = gw + ((size_t)N0 + row) * 64 + as * 8;
            CP_ASYNC16(sb + (BHOF + row * 72 + as * 8) * 2, wH + gb);
        }
    };

    // ldmatrix lane-address components
    int lrow = lane & 7, lm = lane >> 3;
    int aRowOff = lrow + (lm & 1) * 8;
    int aColOff = (lm >> 1) * 8;
    int bRowOff = (lm >> 1) * 8 + lrow;
    int bColOff = (lm & 1) * 8;

    float C[4][4];
#pragma unroll
    for (int nt = 0; nt < 4; nt++)
#pragma unroll
        for (int j = 0; j < 4; j++) C[nt][j] = 0.f;

    stage_issue(0); CP_COMMIT();
    stage_issue(1); CP_COMMIT();

    for (int c = 0; c < NCHK; c++) {
        if (c == NCHK - 1) { CP_WAIT(0); } else { CP_WAIT(1); }
        __syncthreads();   // all warps done with chunk c-1 -> its slot is free
        if (c + 2 < NCHK) { stage_issue(c + 2); CP_COMMIT(); }
        uint32_t base = su + (c - (c / 3) * 3) * (STG * 2);
#pragma unroll
        for (int kk = 0; kk < 4; kk++) {
            unsigned ah[4];
            uint32_t ad = base + ((wm * 16 + aRowOff) * 72 + kk * 16 + aColOff) * 2;
            LDMX4(ah[0], ah[1], ah[2], ah[3], ad);
            unsigned bh[4][2];
#pragma unroll
            for (int ntp = 0; ntp < 2; ntp++) {
                uint32_t bd = base + (BHOF + (wn * 32 + ntp * 16 + bRowOff) * 72 + kk * 16 + bColOff) * 2;
                LDMX4(bh[2*ntp][0], bh[2*ntp][1], bh[2*ntp+1][0], bh[2*ntp+1][1], bd);
            }
            // 4 independent depth-1 MMA chains
#pragma unroll
            for (int nt = 0; nt < 4; nt++)
                mma16816(C[nt], ah, bh[nt][0], bh[nt][1]);
        }
    }

    // epilogue: bias + relu; write fp16 (padded) or fp32 (last layer)
    int row0 = R0 + wm * 16 + g;
#pragma unroll
    for (int nt = 0; nt < 4; nt++) {
        int lc = wn * 32 + nt * 8 + tg * 2;
        int col = N0 + lc;
        float b0v = sbias[lc], b1v = sbias[lc + 1];
        float v00 = fmaxf(C[nt][0] + b0v, 0.f);
        float v01 = fmaxf(C[nt][1] + b1v, 0.f);
        float v10 = fmaxf(C[nt][2] + b0v, 0.f);
        float v11 = fmaxf(C[nt][3] + b1v, 0.f);
        int s0 = row0 >> 4, l0 = row0 & 15;
        int s1 = (row0 + 8) >> 4, l1 = (row0 + 8) & 15;
        if (outF) {
            *(float2*)(outF + ((size_t)s0 * L + l0) * H1 + col) = make_float2(v00, v01);
            *(float2*)(outF + ((size_t)s1 * L + l1) * H1 + col) = make_float2(v10, v11);
        } else {
            size_t o0 = ((size_t)s0 * LP + l0 + 2) * H1 + col;
            size_t o1 = ((size_t)s1 * LP + l1 + 2) * H1 + col;
            *(__half2*)(outH + o0) = __halves2half2(__float2half_rn(v00), __float2half_rn(v01));
            *(__half2*)(outH + o1) = __halves2half2(__float2half_rn(v10), __float2half_rn(v11));
        }
    }
}

// ================= mean over tokens (+ residual) =================
__global__ void k_emb() {
    int r = blockIdx.x, f = threadIdx.x;
    float acc = 0.f;
#pragma unroll
    for (int l = 0; l < 16; l++)
        acc += g_out3[(size_t)(r * L + l) * H1 + f] + g_xe[(size_t)(r * L + l) * H1 + f];
    g_emb[r * H1 + f] = acc * (1.f / 16.f);
}

// ===== fused tail: qbits + pairwise MLP + sparse desc_sim, per (q, 8 p's) =====
__global__ void k_fused(const float* __restrict__ b1, const float* __restrict__ b2,
                        const float* __restrict__ w3) {
    __shared__ unsigned qm[NW];
    __shared__ float sqe[H1];
    __shared__ float red[8];
    int q = blockIdx.y, pg = blockIdx.x;
    int t = threadIdx.x, lane = t & 31, wid = t >> 5;
    unsigned qw = g_mask[q * NW + t];
    qm[t] = qw;
    sqe[t] = fmaxf(g_emb[q * H1 + t], 0.f);
    int pc = __popc(qw);
#pragma unroll
    for (int off = 16; off; off >>= 1) pc += __shfl_down_sync(0xffffffffu, pc, off);
    if (lane == 0) red[wid] = (float)pc;
    __syncthreads();
    float qbits = 0.f;
#pragma unroll
    for (int k = 0; k < 8; k++) qbits += red[k];

    int p = pg * 8 + wid;
    const float* pe = g_emb + (size_t)(BQ + p) * H1;
    int j = lane;
    float acc = b1[j];
#pragma unroll 4
    for (int i = 0; i < 256; i++) acc += sqe[i] * g_w1T[i * 32 + j];
#pragma unroll 4
    for (int i = 0; i < 256; i++) acc += fmaxf(pe[i], 0.f) * g_w1T[(256 + i) * 32 + j];
    float h2v = fmaxf(acc, 0.f);
    float acc3 = b2[j];
#pragma unroll
    for (int m = 0; m < 32; m++)
        acc3 += __shfl_sync(0xffffffffu, h2v, m) * g_w2T[m * 32 + j];
    float h3v = fmaxf(acc3, 0.f);
    float hj[32];
#pragma unroll
    for (int m = 0; m < 32; m++) hj[m] = __shfl_sync(0xffffffffu, h3v, m);

    const unsigned* pm = g_mask + (size_t)(BQ + p) * NW;
    float s = 0.f;
    int cnt = 0;
    for (int w8 = 0; w8 < 8; w8++) {
        int wi = w8 * 32 + lane;
        unsigned m = qm[wi] & pm[wi];
        cnt += __popc(m);
        while (m) {
            int b = __ffs(m) - 1;
            m &= m - 1;
            int c = wi * 32 + b;
            const float4* r4 = (const float4*)(w3 + (size_t)c * 32);
            float wv = 0.f;
#pragma unroll
            for (int j4 = 0; j4 < 8; j4++) {
                float4 v = r4[j4];
                wv += hj[j4*4] * v.x + hj[j4*4+1] * v.y + hj[j4*4+2] * v.z + hj[j4*4+3] * v.w;
            }
            s += (wv >= 0.f) ? wv : wv * 0.125f;
        }
    }
#pragma unroll
    for (int off = 16; off; off >>= 1) {
        s += __shfl_down_sync(0xffffffffu, s, off);
        cnt += __shfl_down_sync(0xffffffffu, cnt, off);
    }
    if (lane == 0) g_desc[q * 256 + p] = ((float)cnt + s) / qbits;
}

// ================= normalization + geo fusion =================
__global__ void k_final(const float* __restrict__ qloc, const float* __restrict__ ploc,
                        const float* __restrict__ pa, const float* __restrict__ pb,
                        const float* __restrict__ pc, const float* __restrict__ pd,
                        float* __restrict__ out) {
    __shared__ float red[256];
    int q = blockIdx.x, p = threadIdx.x;
    float ds = g_desc[q * 256 + p];
    red[p] = ds;
    __syncthreads();
    for (int s = 128; s > 0; s >>= 1) {
        if (p < s) red[p] += red[p + s];
        __syncthreads();
    }
    float mean = red[0] / 256.f;
    __syncthreads();
    float df = ds - mean;
    red[p] = df * df;
    __syncthreads();
    for (int s = 128; s > 0; s >>= 1) {
        if (p < s) red[p] += red[p + s];
        __syncthreads();
    }
    float stddev = sqrtf(red[0] / 255.f);
    float dsn = df / (stddev + 1e-6f);
    float dx = qloc[q * 2] - ploc[p * 2];
    float dy = qloc[q * 2 + 1] - ploc[p * 2 + 1];
    float dist = sqrtf(dx * dx + dy * dy);
    float A = *pa, B = *pb, Cc2 = *pc, D = *pd;
    float sig = 1.f / (1.f + expf(-(A * dsn + B)));
    out[q * 256 + p] = (Cc2 - sig) * (-logf(dist + 1.f) - D);
}

// ================= launch =================
extern "C" void kernel_launch(void* const* d_in, const int* in_sizes, int n_in,
                              void* d_out, int out_size) {
    const float* query_x  = (const float*)d_in[0];
    const float* query_loc = (const float*)d_in[1];
    const float* poi_x    = (const float*)d_in[2];
    const float* poi_loc  = (const float*)d_in[3];
    const float* enc_w    = (const float*)d_in[4];
    const float* cw1 = (const float*)d_in[5];  const float* cb1 = (const float*)d_in[6];
    const float* cw2 = (const float*)d_in[7];  const float* cb2 = (const float*)d_in[8];
    const float* cw3 = (const float*)d_in[9];  const float* cb3 = (const float*)d_in[10];
    const float* dw1 = (const float*)d_in[11]; const float* db1 = (const float*)d_in[12];
    const float* dw2 = (const float*)d_in[13]; const float* db2 = (const float*)d_in[14];
    const float* dw3 = (const float*)d_in[15];
    const float* pa = (const float*)d_in[16];
    const float* pb = (const float*)d_in[17];
    const float* pc = (const float*)d_in[18];
    const float* pd = (const float*)d_in[19];
    float* out = (float*)d_out;

    float *p_out3;
    __half *p_wH, *p_hAH, *p_hBH;
    cudaGetSymbolAddress((void**)&p_wH, g_wH);
    cudaGetSymbolAddress((void**)&p_hAH, g_hAH);
    cudaGetSymbolAddress((void**)&p_hBH, g_hBH);
    cudaGetSymbolAddress((void**)&p_out3, g_out3);

    cudaFuncSetAttribute(k_conv_mma, cudaFuncAttributeMaxDynamicSharedMemorySize, CONV_SMEM);

    // fused prep
    k_prep<<<ZA + ZB + ZC, 256>>>(dw1, dw2, cw1, cw2, cw3, enc_w);
    // encode + blooms (coalesced)
    k_encode<<<dim3(NB, L), 256>>>(query_x, poi_x);
    // conv stack: pure fp16 (Ah*Wh), 512-thr CTAs, K64, 3-stage ring (R12)
    dim3 cgrid(NB * L / 64, 2);
    k_conv_mma<<<cgrid, 512, CONV_SMEM>>>(p_hAH, p_wH, cb1, p_hBH, (float*)0);
    k_conv_mma<<<cgrid, 512, CONV_SMEM>>>(p_hBH, p_wH + H1 * KTOT, cb2, p_hAH, (float*)0);
    k_conv_mma<<<cgrid, 512, CONV_SMEM>>>(p_hAH, p_wH + 2 * H1 * KTOT, cb3, (__half*)0, p_out3);
    // tail
    k_emb<<<NB, 256>>>();
    k_fused<<<dim3(32, 32), 256>>>(db1, db2, dw3);
    k_final<<<BQ, 256>>>(query_loc, poi_loc, pa, pb, pc, pd, out);
}

// round 15
// speedup vs baseline: 1.2978x; 1.1660x over previous
#include <cuda_runtime.h>
#include <cuda_fp16.h>
#include <math.h>
#include <stdint.h>

#define BQ 32
#define BP 256
#define NB 288
#define L 16
#define LP 20          // padded token length (2 zeros each side)
#define CIN 8192
#define H1 256
#define H2 32
#define NW (CIN/32)
#define KTOT 1280      // conv GEMM K = 5*256
#define NCHK 20        // K chunks of 64

// ================= scratch (device globals) =================
__device__ __half   g_encTh[CIN*H1];   // enc_w transposed, fp16
__device__ __half   g_w3h[CIN*H2];     // dec_w3, fp16 [c][32]
__device__ __half   g_wH[3*H1*KTOT];   // per layer: chunk64-major [c][o][64]
__device__ float    g_w1T[2*H1*H2];
__device__ float    g_w2T[H2*H2];
__device__ float    g_xe[NB*L*H1];
__device__ __half   g_hAH[NB*LP*H1];   // activations, fp16 (padded)
__device__ __half   g_hBH[NB*LP*H1];
__device__ float    g_out3[NB*L*H1];
__device__ unsigned g_mask[NB*NW];
__device__ float    g_emb[NB*H1];
__device__ float    g_desc[BQ*BP];

// ================= fused prep (3 zones) =================
#define ZA 2880
#define ZB 3840
#define ZC 2048
__global__ void k_prep(const float* __restrict__ dw1, const float* __restrict__ dw2,
                       const float* __restrict__ cw1, const float* __restrict__ cw2,
                       const float* __restrict__ cw3, const float* __restrict__ enc_w,
                       const float* __restrict__ dw3) {
    __shared__ float tile[32][33];
    int bb = blockIdx.x, tid = threadIdx.x;
    if (bb < ZA) {
        int i = bb * 256 + tid;
        if (i < NB * NW) g_mask[i] = 0u;
        ((unsigned*)g_hAH)[i] = 0u;
        ((unsigned*)g_hBH)[i] = 0u;
        if (i < 512 * 32) { int r = i >> 5, j = i & 31; g_w1T[i] = dw1[j * 512 + r]; }
        if (i < 32 * 32)  { int m = i >> 5, j = i & 31; g_w2T[i] = dw2[j * 32 + m]; }
        if (i < CIN * H2) {  // dec_w3 [8192 out][32 in] -> fp16 [c][j] : g_w3h[c*32+j]=dw3[c*32+j]
            g_w3h[i] = __float2half_rn(dw3[i]);
        }
    } else if (bb < ZA + ZB) {
        int idx = (bb - ZA) * 256 + tid;
        int layer = idx / (H1 * KTOT);
        int r = idx - layer * (H1 * KTOT);
        int o = r / KTOT, k = r - o * KTOT;
        int dl = k >> 8, i = k & 255;
        const float* src = (layer == 0) ? cw1 : (layer == 1) ? cw2 : cw3;
        float v = src[o * 1280 + i * 5 + dl];
        int c = k >> 6, w = k & 63;   // chunk64-major
        size_t dst = (size_t)layer * (H1 * KTOT) + (size_t)c * (H1 * 64) + o * 64 + w;
        g_wH[dst] = __float2half_rn(v);
    } else {
        int cb = bb - ZA - ZB;
        int c0 = (cb & 255) * 32, r0 = (cb >> 8) * 32;
        int tx = tid & 31, ty = tid >> 5;
        int c = c0 + tx;
#pragma unroll
        for (int dr = ty; dr < 32; dr += 8)
            tile[dr][tx] = enc_w[(size_t)(r0 + dr) * CIN + c];
        __syncthreads();
        int r = r0 + tx;
#pragma unroll
        for (int dc = ty; dc < 32; dc += 8)
            g_encTh[(size_t)(c0 + dc) * H1 + r] = __float2half_rn(tile[tx][dc]);
    }
}

// ======= encode + bloom: coalesced x reads, fp16 encT gather =======
#define NZCAP 2048
__global__ void k_encode(const float* __restrict__ qx, const float* __restrict__ px) {
    __shared__ unsigned short sidx[NZCAP];
    __shared__ int wsum[8];
    __shared__ unsigned smask[256];
    int r = blockIdx.x, l = blockIdx.y, t = threadIdx.x;
    int lane = t & 31, w = t >> 5;
    const float* x = (r < BQ) ? (qx + (size_t)(r * L + l) * CIN)
                              : (px + (size_t)((r - BQ) * L + l) * CIN);
    smask[t] = 0u;
    __syncthreads();
    const float4* x4 = (const float4*)x;
    unsigned nib = 0;
#pragma unroll
    for (int j = 0; j < 8; j++) {
        float4 v = x4[j * 256 + t];   // coalesced: lane-contiguous 16B
        unsigned b = 0;
        if (v.x != 0.f) b |= 1u;
        if (v.y != 0.f) b |= 2u;
        if (v.z != 0.f) b |= 4u;
        if (v.w != 0.f) b |= 8u;
        nib |= b << (j * 4);
        if (b) atomicOr(&smask[j * 32 + (t >> 3)], b << ((t & 7) * 4));
    }
    int cnt = __popc(nib);
    int pref = cnt;
#pragma unroll
    for (int d = 1; d < 32; d <<= 1) {
        int v = __shfl_up_sync(0xffffffffu, pref, d);
        if (lane >= d) pref += v;
    }
    if (lane == 31) wsum[w] = pref;
    __syncthreads();
    int wbase = 0, total = 0;
#pragma unroll
    for (int k = 0; k < 8; k++) {
        int v = wsum[k];
        if (k < w) wbase += v;
        total += v;
    }
    if (total > NZCAP) total = NZCAP;
    int base = wbase + pref - cnt;
    unsigned m = nib;
    while (m && base < NZCAP) {
        int bpos = __ffs(m) - 1;
        m &= m - 1;
        int j = bpos >> 2, k = bpos & 3;
        sidx[base++] = (unsigned short)(j * 1024 + t * 4 + k);
    }
    __syncthreads();
    unsigned mw = smask[t];
    if (mw) atomicOr(&g_mask[r * NW + t], mw);
    // gather-accumulate (fp16 table, fp32 accum, 4 independent chains)
    float a0 = 0.f, a1 = 0.f, a2 = 0.f, a3 = 0.f;
    int j = 0;
    for (; j + 4 <= total; j += 4) {
        a0 += __half2float(g_encTh[(int)sidx[j + 0] * H1 + t]);
        a1 += __half2float(g_encTh[(int)sidx[j + 1] * H1 + t]);
        a2 += __half2float(g_encTh[(int)sidx[j + 2] * H1 + t]);
        a3 += __half2float(g_encTh[(int)sidx[j + 3] * H1 + t]);
    }
    for (; j < total; j++) a0 += __half2float(g_encTh[(int)sidx[j] * H1 + t]);
    float acc = (a0 + a1) + (a2 + a3);
    g_xe[(size_t)(r * L + l) * H1 + t] = acc;
    g_hAH[((size_t)r * LP + (l + 2)) * H1 + t] = __float2half_rn(acc);
}

// ================= conv via mma.sync pure fp16 GEMM (R12/R14-exact) =================
#define STG   13824   // halves per stage: AH 4608 | BH 9216
#define BHOF  4608
#define NSTAGE 3
#define CONV_SMEM (NSTAGE*STG*2 + 512)

#define CP_ASYNC16(sa, gp) asm volatile("cp.async.cg.shared.global [%0], [%1], 16;" :: "r"(sa), "l"(gp))
#define CP_COMMIT()        asm volatile("cp.async.commit_group;")
#define CP_WAIT(n)         asm volatile("cp.async.wait_group %0;" :: "n"(n))
#define LDMX4(r0, r1, r2, r3, addr) \
    asm volatile("ldmatrix.sync.aligned.m8n8.x4.shared.b16 {%0,%1,%2,%3}, [%4];" \
        : "=r"(r0), "=r"(r1), "=r"(r2), "=r"(r3) : "r"(addr))

__device__ __forceinline__ uint32_t smem_u32(const void* p) {
    uint32_t a;
    asm("{ .reg .u64 t; cvta.to.shared.u64 t, %1; cvt.u32.u64 %0, t; }" : "=r"(a) : "l"(p));
    return a;
}

__device__ __forceinline__ void mma16816(float* c, const unsigned* a,
                                         unsigned b0, unsigned b1) {
    asm volatile(
        "mma.sync.aligned.m16n8k16.row.col.f32.f16.f16.f32 "
        "{%0,%1,%2,%3}, {%4,%5,%6,%7}, {%8,%9}, {%0,%1,%2,%3};"
        : "+f"(c[0]), "+f"(c[1]), "+f"(c[2]), "+f"(c[3])
        : "r"(a[0]), "r"(a[1]), "r"(a[2]), "r"(a[3]), "r"(b0), "r"(b1));
}

__global__ void __launch_bounds__(512) k_conv_mma(
    const __half* __restrict__ inH,
    const __half* __restrict__ wH,
    const float* __restrict__ bias,
    __half* __restrict__ outH,
    float* __restrict__ outF) {
    extern __shared__ __half sm[];
    float* sbias = (float*)(sm + NSTAGE * STG);
    uint32_t su = smem_u32(sm);
    int tid = threadIdx.x;
    int wid = tid >> 5, lane = tid & 31;
    int wm = wid >> 2, wn = wid & 3;
    int g = lane >> 2, tg = lane & 3;
    int R0 = blockIdx.x * 64;
    int N0 = blockIdx.y * 128;

    if (tid < 128) sbias[tid] = bias[N0 + tid];

    int ar = tid >> 3, as = tid & 7;
    int grow = R0 + ar;
    int gs = grow >> 4, gl = grow & 15;

    auto stage_issue = [&](int c) {
        int st = c - (c / 3) * 3;
        uint32_t sb = su + st * (STG * 2);
        int dl = c >> 2, i0 = (c & 3) * 64;
        size_t ga = ((size_t)gs * LP + gl + dl) * H1 + i0 + as * 8;
        CP_ASYNC16(sb + (ar * 72 + as * 8) * 2, inH + ga);
        size_t gw = (size_t)c * (H1 * 64);
#pragma unroll
        for (int hh = 0; hh < 2; hh++) {
            int row = hh * 64 + ar;
            size_t gb = gw + ((size_t)N0 + row) * 64 + as * 8;
            CP_ASYNC16(sb + (BHOF + row * 72 + as * 8) * 2, wH + gb);
        }
    };

    int lrow = lane & 7, lm = lane >> 3;
    int aRowOff = lrow + (lm & 1) * 8;
    int aColOff = (lm >> 1) * 8;
    int bRowOff = (lm >> 1) * 8 + lrow;
    int bColOff = (lm & 1) * 8;

    float C[4][4];
#pragma unroll
    for (int nt = 0; nt < 4; nt++)
#pragma unroll
        for (int j = 0; j < 4; j++) C[nt][j] = 0.f;

    stage_issue(0); CP_COMMIT();
    stage_issue(1); CP_COMMIT();

    for (int c = 0; c < NCHK; c++) {
        if (c == NCHK - 1) { CP_WAIT(0); } else { CP_WAIT(1); }
        __syncthreads();
        if (c + 2 < NCHK) { stage_issue(c + 2); CP_COMMIT(); }
        uint32_t base = su + (c - (c / 3) * 3) * (STG * 2);
#pragma unroll
        for (int kk = 0; kk < 4; kk++) {
            unsigned ah[4];
            uint32_t ad = base + ((wm * 16 + aRowOff) * 72 + kk * 16 + aColOff) * 2;
            LDMX4(ah[0], ah[1], ah[2], ah[3], ad);
            unsigned bh[4][2];
#pragma unroll
            for (int ntp = 0; ntp < 2; ntp++) {
                uint32_t bd = base + (BHOF + (wn * 32 + ntp * 16 + bRowOff) * 72 + kk * 16 + bColOff) * 2;
                LDMX4(bh[2*ntp][0], bh[2*ntp][1], bh[2*ntp+1][0], bh[2*ntp+1][1], bd);
            }
#pragma unroll
            for (int nt = 0; nt < 4; nt++)
                mma16816(C[nt], ah, bh[nt][0], bh[nt][1]);
        }
    }

    int row0 = R0 + wm * 16 + g;
#pragma unroll
    for (int nt = 0; nt < 4; nt++) {
        int lc = wn * 32 + nt * 8 + tg * 2;
        int col = N0 + lc;
        float b0v = sbias[lc], b1v = sbias[lc + 1];
        float v00 = fmaxf(C[nt][0] + b0v, 0.f);
        float v01 = fmaxf(C[nt][1] + b1v, 0.f);
        float v10 = fmaxf(C[nt][2] + b0v, 0.f);
        float v11 = fmaxf(C[nt][3] + b1v, 0.f);
        int s0 = row0 >> 4, l0 = row0 & 15;
        int s1 = (row0 + 8) >> 4, l1 = (row0 + 8) & 15;
        if (outF) {
            *(float2*)(outF + ((size_t)s0 * L + l0) * H1 + col) = make_float2(v00, v01);
            *(float2*)(outF + ((size_t)s1 * L + l1) * H1 + col) = make_float2(v10, v11);
        } else {
            size_t o0 = ((size_t)s0 * LP + l0 + 2) * H1 + col;
            size_t o1 = ((size_t)s1 * LP + l1 + 2) * H1 + col;
            *(__half2*)(outH + o0) = __halves2half2(__float2half_rn(v00), __float2half_rn(v01));
            *(__half2*)(outH + o1) = __halves2half2(__float2half_rn(v10), __float2half_rn(v11));
        }
    }
}

// ================= mean over tokens (+ residual) =================
__global__ void k_emb() {
    int r = blockIdx.x, f = threadIdx.x;
    float acc = 0.f;
#pragma unroll
    for (int l = 0; l < 16; l++)
        acc += g_out3[(size_t)(r * L + l) * H1 + f] + g_xe[(size_t)(r * L + l) * H1 + f];
    g_emb[r * H1 + f] = acc * (1.f / 16.f);
}

// ===== fused tail: qbits + pairwise MLP + sparse desc_sim (fp16 w3) =====
__global__ void k_fused(const float* __restrict__ b1, const float* __restrict__ b2) {
    __shared__ unsigned qm[NW];
    __shared__ float sqe[H1];
    __shared__ float red[8];
    int q = blockIdx.y, pg = blockIdx.x;
    int t = threadIdx.x, lane = t & 31, wid = t >> 5;
    unsigned qw = g_mask[q * NW + t];
    qm[t] = qw;
    sqe[t] = fmaxf(g_emb[q * H1 + t], 0.f);
    int pc = __popc(qw);
#pragma unroll
    for (int off = 16; off; off >>= 1) pc += __shfl_down_sync(0xffffffffu, pc, off);
    if (lane == 0) red[wid] = (float)pc;
    __syncthreads();
    float qbits = 0.f;
#pragma unroll
    for (int k = 0; k < 8; k++) qbits += red[k];

    int p = pg * 8 + wid;
    const float* pe = g_emb + (size_t)(BQ + p) * H1;
    int j = lane;
    float acc = b1[j];
#pragma unroll 4
    for (int i = 0; i < 256; i++) acc += sqe[i] * g_w1T[i * 32 + j];
#pragma unroll 4
    for (int i = 0; i < 256; i++) acc += fmaxf(pe[i], 0.f) * g_w1T[(256 + i) * 32 + j];
    float h2v = fmaxf(acc, 0.f);
    float acc3 = b2[j];
#pragma unroll
    for (int m = 0; m < 32; m++)
        acc3 += __shfl_sync(0xffffffffu, h2v, m) * g_w2T[m * 32 + j];
    float h3v = fmaxf(acc3, 0.f);
    float hj[32];
#pragma unroll
    for (int m = 0; m < 32; m++) hj[m] = __shfl_sync(0xffffffffu, h3v, m);

    const unsigned* pm = g_mask + (size_t)(BQ + p) * NW;
    float s = 0.f;
    int cnt = 0;
    for (int w8 = 0; w8 < 8; w8++) {
        int wi = w8 * 32 + lane;
        unsigned m = qm[wi] & pm[wi];
        cnt += __popc(m);
        while (m) {
            int b = __ffs(m) - 1;
            m &= m - 1;
            int c = wi * 32 + b;
            const uint4* r4 = (const uint4*)(g_w3h + (size_t)c * 32);
            float wv = 0.f;
#pragma unroll
            for (int q4 = 0; q4 < 2; q4++) {
                uint4 v = r4[q4];
                unsigned ww[4] = {v.x, v.y, v.z, v.w};
#pragma unroll
                for (int k2 = 0; k2 < 4; k2++) {
                    float2 f = __half22float2(*(const __half2*)&ww[k2]);
                    int idx = q4 * 8 + k2 * 2;
                    wv += hj[idx] * f.x + hj[idx + 1] * f.y;
                }
            }
            s += (wv >= 0.f) ? wv : wv * 0.125f;
        }
    }
#pragma unroll
    for (int off = 16; off; off >>= 1) {
        s += __shfl_down_sync(0xffffffffu, s, off);
        cnt += __shfl_down_sync(0xffffffffu, cnt, off);
    }
    if (lane == 0) g_desc[q * 256 + p] = ((float)cnt + s) / qbits;
}

// ================= normalization + geo fusion =================
__global__ void k_final(const float* __restrict__ qloc, const float* __restrict__ ploc,
                        const float* __restrict__ pa, const float* __restrict__ pb,
                        const float* __restrict__ pc, const float* __restrict__ pd,
                        float* __restrict__ out) {
    __shared__ float red[256];
    int q = blockIdx.x, p = threadIdx.x;
    float ds = g_desc[q * 256 + p];
    red[p] = ds;
    __syncthreads();
    for (int s = 128; s > 0; s >>= 1) {
        if (p < s) red[p] += red[p + s];
        __syncthreads();
    }
    float mean = red[0] / 256.f;
    __syncthreads();
    float df = ds - mean;
    red[p] = df * df;
    __syncthreads();
    for (int s = 128; s > 0; s >>= 1) {
        if (p < s) red[p] += red[p + s];
        __syncthreads();
    }
    float stddev = sqrtf(red[0] / 255.f);
    float dsn = df / (stddev + 1e-6f);
    float dx = qloc[q * 2] - ploc[p * 2];
    float dy = qloc[q * 2 + 1] - ploc[p * 2 + 1];
    float dist = sqrtf(dx * dx + dy * dy);
    float A = *pa, B = *pb, Cc2 = *pc, D = *pd;
    float sig = 1.f / (1.f + expf(-(A * dsn + B)));
    out[q * 256 + p] = (Cc2 - sig) * (-logf(dist + 1.f) - D);
}

// ================= launch =================
extern "C" void kernel_launch(void* const* d_in, const int* in_sizes, int n_in,
                              void* d_out, int out_size) {
    const float* query_x  = (const float*)d_in[0];
    const float* query_loc = (const float*)d_in[1];
    const float* poi_x    = (const float*)d_in[2];
    const float* poi_loc  = (const float*)d_in[3];
    const float* enc_w    = (const float*)d_in[4];
    const float* cw1 = (const float*)d_in[5];  const float* cb1 = (const float*)d_in[6];
    const float* cw2 = (const float*)d_in[7];  const float* cb2 = (const float*)d_in[8];
    const float* cw3 = (const float*)d_in[9];  const float* cb3 = (const float*)d_in[10];
    const float* dw1 = (const float*)d_in[11]; const float* db1 = (const float*)d_in[12];
    const float* dw2 = (const float*)d_in[13]; const float* db2 = (const float*)d_in[14];
    const float* dw3 = (const float*)d_in[15];
    const float* pa = (const float*)d_in[16];
    const float* pb = (const float*)d_in[17];
    const float* pc = (const float*)d_in[18];
    const float* pd = (const float*)d_in[19];
    float* out = (float*)d_out;

    float *p_out3;
    __half *p_wH, *p_hAH, *p_hBH;
    cudaGetSymbolAddress((void**)&p_wH, g_wH);
    cudaGetSymbolAddress((void**)&p_hAH, g_hAH);
    cudaGetSymbolAddress((void**)&p_hBH, g_hBH);
    cudaGetSymbolAddress((void**)&p_out3, g_out3);

    cudaFuncSetAttribute(k_conv_mma, cudaFuncAttributeMaxDynamicSharedMemorySize, CONV_SMEM);

    // fused prep
    k_prep<<<ZA + ZB + ZC, 256>>>(dw1, dw2, cw1, cw2, cw3, enc_w, dw3);
    // encode + blooms (coalesced, fp16 encT)
    k_encode<<<dim3(NB, L), 256>>>(query_x, poi_x);
    // conv stack: pure fp16 (Ah*Wh), 512-thr CTAs, K64, 3-stage ring
    dim3 cgrid(NB * L / 64, 2);
    k_conv_mma<<<cgrid, 512, CONV_SMEM>>>(p_hAH, p_wH, cb1, p_hBH, (float*)0);
    k_conv_mma<<<cgrid, 512, CONV_SMEM>>>(p_hBH, p_wH + H1 * KTOT, cb2, p_hAH, (float*)0);
    k_conv_mma<<<cgrid, 512, CONV_SMEM>>>(p_hAH, p_wH + 2 * H1 * KTOT, cb3, (__half*)0, p_out3);
    // tail
    k_emb<<<NB, 256>>>();
    k_fused<<<dim3(32, 32), 256>>>(db1, db2);
    k_final<<<BQ, 256>>>(query_loc, poi_loc, pa, pb, pc, pd, out);
}

// round 16
// speedup vs baseline: 1.8249x; 1.4061x over previous
#include <cuda_runtime.h>
#include <cuda_fp16.h>
#include <math.h>
#include <stdint.h>

#define BQ 32
#define BP 256
#define NB 288
#define L 16
#define LP 20          // padded token length (2 zeros each side)
#define CIN 8192
#define H1 256
#define H2 32
#define NW (CIN/32)
#define KTOT 1280      // conv GEMM K = 5*256
#define NCHK 20        // K chunks of 64

// ================= scratch (device globals) =================
__device__ __half   g_encTh[CIN*H1];   // enc_w transposed, fp16
__device__ __half   g_w3h[CIN*H2];     // dec_w3, fp16 [c][32]
__device__ __half   g_wH[3*H1*KTOT];   // per layer: chunk64-major [c][o][64]
__device__ float    g_w1T[2*H1*H2];
__device__ float    g_w2T[H2*H2];
__device__ float    g_xe[NB*L*H1];
__device__ __half   g_hAH[NB*LP*H1];   // activations, fp16 (padded)
__device__ __half   g_hBH[NB*LP*H1];
__device__ float    g_out3[NB*L*H1];
__device__ unsigned g_mask[NB*NW];
__device__ float    g_uv[NB*H2];       // factored layer-1 partials u[q]/v[p]
__device__ float    g_desc[BQ*BP];

// ================= fused prep (3 zones) =================
#define ZA 2880
#define ZB 3840
#define ZC 2048
__global__ void k_prep(const float* __restrict__ dw1, const float* __restrict__ dw2,
                       const float* __restrict__ cw1, const float* __restrict__ cw2,
                       const float* __restrict__ cw3, const float* __restrict__ enc_w,
                       const float* __restrict__ dw3) {
    __shared__ float tile[32][33];
    int bb = blockIdx.x, tid = threadIdx.x;
    if (bb < ZA) {
        int i = bb * 256 + tid;
        if (i < NB * NW) g_mask[i] = 0u;
        ((unsigned*)g_hAH)[i] = 0u;
        ((unsigned*)g_hBH)[i] = 0u;
        if (i < 512 * 32) { int r = i >> 5, j = i & 31; g_w1T[i] = dw1[j * 512 + r]; }
        if (i < 32 * 32)  { int m = i >> 5, j = i & 31; g_w2T[i] = dw2[j * 32 + m]; }
        if (i < CIN * H2) g_w3h[i] = __float2half_rn(dw3[i]);
    } else if (bb < ZA + ZB) {
        int idx = (bb - ZA) * 256 + tid;
        int layer = idx / (H1 * KTOT);
        int r = idx - layer * (H1 * KTOT);
        int o = r / KTOT, k = r - o * KTOT;
        int dl = k >> 8, i = k & 255;
        const float* src = (layer == 0) ? cw1 : (layer == 1) ? cw2 : cw3;
        float v = src[o * 1280 + i * 5 + dl];
        int c = k >> 6, w = k & 63;   // chunk64-major
        size_t dst = (size_t)layer * (H1 * KTOT) + (size_t)c * (H1 * 64) + o * 64 + w;
        g_wH[dst] = __float2half_rn(v);
    } else {
        int cb = bb - ZA - ZB;
        int c0 = (cb & 255) * 32, r0 = (cb >> 8) * 32;
        int tx = tid & 31, ty = tid >> 5;
        int c = c0 + tx;
#pragma unroll
        for (int dr = ty; dr < 32; dr += 8)
            tile[dr][tx] = enc_w[(size_t)(r0 + dr) * CIN + c];
        __syncthreads();
        int r = r0 + tx;
#pragma unroll
        for (int dc = ty; dc < 32; dc += 8)
            g_encTh[(size_t)(c0 + dc) * H1 + r] = __float2half_rn(tile[tx][dc]);
    }
}

// ======= encode + bloom: coalesced x reads, fp16 encT gather =======
#define NZCAP 2048
__global__ void k_encode(const float* __restrict__ qx, const float* __restrict__ px) {
    __shared__ unsigned short sidx[NZCAP];
    __shared__ int wsum[8];
    __shared__ unsigned smask[256];
    int r = blockIdx.x, l = blockIdx.y, t = threadIdx.x;
    int lane = t & 31, w = t >> 5;
    const float* x = (r < BQ) ? (qx + (size_t)(r * L + l) * CIN)
                              : (px + (size_t)((r - BQ) * L + l) * CIN);
    smask[t] = 0u;
    __syncthreads();
    const float4* x4 = (const float4*)x;
    unsigned nib = 0;
#pragma unroll
    for (int j = 0; j < 8; j++) {
        float4 v = x4[j * 256 + t];   // coalesced: lane-contiguous 16B
        unsigned b = 0;
        if (v.x != 0.f) b |= 1u;
        if (v.y != 0.f) b |= 2u;
        if (v.z != 0.f) b |= 4u;
        if (v.w != 0.f) b |= 8u;
        nib |= b << (j * 4);
        if (b) atomicOr(&smask[j * 32 + (t >> 3)], b << ((t & 7) * 4));
    }
    int cnt = __popc(nib);
    int pref = cnt;
#pragma unroll
    for (int d = 1; d < 32; d <<= 1) {
        int v = __shfl_up_sync(0xffffffffu, pref, d);
        if (lane >= d) pref += v;
    }
    if (lane == 31) wsum[w] = pref;
    __syncthreads();
    int wbase = 0, total = 0;
#pragma unroll
    for (int k = 0; k < 8; k++) {
        int v = wsum[k];
        if (k < w) wbase += v;
        total += v;
    }
    if (total > NZCAP) total = NZCAP;
    int base = wbase + pref - cnt;
    unsigned m = nib;
    while (m && base < NZCAP) {
        int bpos = __ffs(m) - 1;
        m &= m - 1;
        int j = bpos >> 2, k = bpos & 3;
        sidx[base++] = (unsigned short)(j * 1024 + t * 4 + k);
    }
    __syncthreads();
    unsigned mw = smask[t];
    if (mw) atomicOr(&g_mask[r * NW + t], mw);
    // gather-accumulate (fp16 table, fp32 accum, 4 independent chains)
    float a0 = 0.f, a1 = 0.f, a2 = 0.f, a3 = 0.f;
    int j = 0;
    for (; j + 4 <= total; j += 4) {
        a0 += __half2float(g_encTh[(int)sidx[j + 0] * H1 + t]);
        a1 += __half2float(g_encTh[(int)sidx[j + 1] * H1 + t]);
        a2 += __half2float(g_encTh[(int)sidx[j + 2] * H1 + t]);
        a3 += __half2float(g_encTh[(int)sidx[j + 3] * H1 + t]);
    }
    for (; j < total; j++) a0 += __half2float(g_encTh[(int)sidx[j] * H1 + t]);
    float acc = (a0 + a1) + (a2 + a3);
    g_xe[(size_t)(r * L + l) * H1 + t] = acc;
    g_hAH[((size_t)r * LP + (l + 2)) * H1 + t] = __float2half_rn(acc);
}

// ================= conv via mma.sync pure fp16 GEMM (R12/R14-exact) =================
#define STG   13824   // halves per stage: AH 4608 | BH 9216
#define BHOF  4608
#define NSTAGE 3
#define CONV_SMEM (NSTAGE*STG*2 + 512)

#define CP_ASYNC16(sa, gp) asm volatile("cp.async.cg.shared.global [%0], [%1], 16;" :: "r"(sa), "l"(gp))
#define CP_COMMIT()        asm volatile("cp.async.commit_group;")
#define CP_WAIT(n)         asm volatile("cp.async.wait_group %0;" :: "n"(n))
#define LDMX4(r0, r1, r2, r3, addr) \
    asm volatile("ldmatrix.sync.aligned.m8n8.x4.shared.b16 {%0,%1,%2,%3}, [%4];" \
        : "=r"(r0), "=r"(r1), "=r"(r2), "=r"(r3) : "r"(addr))

__device__ __forceinline__ uint32_t smem_u32(const void* p) {
    uint32_t a;
    asm("{ .reg .u64 t; cvta.to.shared.u64 t, %1; cvt.u32.u64 %0, t; }" : "=r"(a) : "l"(p));
    return a;
}

__device__ __forceinline__ void mma16816(float* c, const unsigned* a,
                                         unsigned b0, unsigned b1) {
    asm volatile(
        "mma.sync.aligned.m16n8k16.row.col.f32.f16.f16.f32 "
        "{%0,%1,%2,%3}, {%4,%5,%6,%7}, {%8,%9}, {%0,%1,%2,%3};"
        : "+f"(c[0]), "+f"(c[1]), "+f"(c[2]), "+f"(c[3])
        : "r"(a[0]), "r"(a[1]), "r"(a[2]), "r"(a[3]), "r"(b0), "r"(b1));
}

__global__ void __launch_bounds__(512) k_conv_mma(
    const __half* __restrict__ inH,
    const __half* __restrict__ wH,
    const float* __restrict__ bias,
    __half* __restrict__ outH,
    float* __restrict__ outF) {
    extern __shared__ __half sm[];
    float* sbias = (float*)(sm + NSTAGE * STG);
    uint32_t su = smem_u32(sm);
    int tid = threadIdx.x;
    int wid = tid >> 5, lane = tid & 31;
    int wm = wid >> 2, wn = wid & 3;
    int g = lane >> 2, tg = lane & 3;
    int R0 = blockIdx.x * 64;
    int N0 = blockIdx.y * 128;

    if (tid < 128) sbias[tid] = bias[N0 + tid];

    int ar = tid >> 3, as = tid & 7;
    int grow = R0 + ar;
    int gs = grow >> 4, gl = grow & 15;

    auto stage_issue = [&](int c) {
        int st = c - (c / 3) * 3;
        uint32_t sb = su + st * (STG * 2);
        int dl = c >> 2, i0 = (c & 3) * 64;
        size_t ga = ((size_t)gs * LP + gl + dl) * H1 + i0 + as * 8;
        CP_ASYNC16(sb + (ar * 72 + as * 8) * 2, inH + ga);
        size_t gw = (size_t)c * (H1 * 64);
#pragma unroll
        for (int hh = 0; hh < 2; hh++) {
            int row = hh * 64 + ar;
            size_t gb = gw + ((size_t)N0 + row) * 64 + as * 8;
            CP_ASYNC16(sb + (BHOF + row * 72 + as * 8) * 2, wH + gb);
        }
    };

    int lrow = lane & 7, lm = lane >> 3;
    int aRowOff = lrow + (lm & 1) * 8;
    int aColOff = (lm >> 1) * 8;
    int bRowOff = (lm >> 1) * 8 + lrow;
    int bColOff = (lm & 1) * 8;

    float C[4][4];
#pragma unroll
    for (int nt = 0; nt < 4; nt++)
#pragma unroll
        for (int j = 0; j < 4; j++) C[nt][j] = 0.f;

    stage_issue(0); CP_COMMIT();
    stage_issue(1); CP_COMMIT();

    for (int c = 0; c < NCHK; c++) {
        if (c == NCHK - 1) { CP_WAIT(0); } else { CP_WAIT(1); }
        __syncthreads();
        if (c + 2 < NCHK) { stage_issue(c + 2); CP_COMMIT(); }
        uint32_t base = su + (c - (c / 3) * 3) * (STG * 2);
#pragma unroll
        for (int kk = 0; kk < 4; kk++) {
            unsigned ah[4];
            uint32_t ad = base + ((wm * 16 + aRowOff) * 72 + kk * 16 + aColOff) * 2;
            LDMX4(ah[0], ah[1], ah[2], ah[3], ad);
            unsigned bh[4][2];
#pragma unroll
            for (int ntp = 0; ntp < 2; ntp++) {
                uint32_t bd = base + (BHOF + (wn * 32 + ntp * 16 + bRowOff) * 72 + kk * 16 + bColOff) * 2;
                LDMX4(bh[2*ntp][0], bh[2*ntp][1], bh[2*ntp+1][0], bh[2*ntp+1][1], bd);
            }
#pragma unroll
            for (int nt = 0; nt < 4; nt++)
                mma16816(C[nt], ah, bh[nt][0], bh[nt][1]);
        }
    }

    int row0 = R0 + wm * 16 + g;
#pragma unroll
    for (int nt = 0; nt < 4; nt++) {
        int lc = wn * 32 + nt * 8 + tg * 2;
        int col = N0 + lc;
        float b0v = sbias[lc], b1v = sbias[lc + 1];
        float v00 = fmaxf(C[nt][0] + b0v, 0.f);
        float v01 = fmaxf(C[nt][1] + b1v, 0.f);
        float v10 = fmaxf(C[nt][2] + b0v, 0.f);
        float v11 = fmaxf(C[nt][3] + b1v, 0.f);
        int s0 = row0 >> 4, l0 = row0 & 15;
        int s1 = (row0 + 8) >> 4, l1 = (row0 + 8) & 15;
        if (outF) {
            *(float2*)(outF + ((size_t)s0 * L + l0) * H1 + col) = make_float2(v00, v01);
            *(float2*)(outF + ((size_t)s1 * L + l1) * H1 + col) = make_float2(v10, v11);
        } else {
            size_t o0 = ((size_t)s0 * LP + l0 + 2) * H1 + col;
            size_t o1 = ((size_t)s1 * LP + l1 + 2) * H1 + col;
            *(__half2*)(outH + o0) = __halves2half2(__float2half_rn(v00), __float2half_rn(v01));
            *(__half2*)(outH + o1) = __halves2half2(__float2half_rn(v10), __float2half_rn(v11));
        }
    }
}

// ===== mean over tokens (+ residual) AND factored MLP layer-1 partials =====
// u[r] = W1q . relu(emb[r])  (r < BQ)  |  v[r] = W1p . relu(emb[r])  (r >= BQ)
__global__ void k_emb() {
    __shared__ float se[H1];
    __shared__ float par[8][32];
    int r = blockIdx.x, f = threadIdx.x;
    float acc = 0.f;
#pragma unroll
    for (int l = 0; l < 16; l++)
        acc += g_out3[(size_t)(r * L + l) * H1 + f] + g_xe[(size_t)(r * L + l) * H1 + f];
    se[f] = fmaxf(acc * (1.f / 16.f), 0.f);
    __syncthreads();
    int j = f & 31, part = f >> 5;
    const float* w = g_w1T + (r < BQ ? 0 : 256 * 32);
    float s = 0.f;
    int i0 = part * 32;
#pragma unroll 8
    for (int i = i0; i < i0 + 32; i++) s += se[i] * w[i * 32 + j];
    par[part][j] = s;
    __syncthreads();
    if (f < 32) {
        float tt = 0.f;
#pragma unroll
        for (int k = 0; k < 8; k++) tt += par[k][f];
        g_uv[r * 32 + f] = tt;
    }
}

// ===== fused tail: qbits + factored MLP + sparse desc_sim (fp16 w3) =====
__global__ void k_fused(const float* __restrict__ b1, const float* __restrict__ b2) {
    __shared__ unsigned qm[NW];
    __shared__ float red[8];
    __shared__ float sw2[H2 * H2];
    __shared__ float suq[H2];
    int q = blockIdx.y, pg = blockIdx.x;
    int t = threadIdx.x, lane = t & 31, wid = t >> 5;
    unsigned qw = g_mask[q * NW + t];
    qm[t] = qw;
    if (t < 32) suq[t] = g_uv[q * 32 + t];
    for (int i = t; i < H2 * H2; i += 256) sw2[i] = g_w2T[i];
    int pc = __popc(qw);
#pragma unroll
    for (int off = 16; off; off >>= 1) pc += __shfl_down_sync(0xffffffffu, pc, off);
    if (lane == 0) red[wid] = (float)pc;
    __syncthreads();
    float qbits = 0.f;
#pragma unroll
    for (int k = 0; k < 8; k++) qbits += red[k];

    int p = pg * 8 + wid;
    // layer 1 (factored): h1[j] = relu(u[q][j] + v[p][j] + b1[j]), j = lane
    float h2v = fmaxf(suq[lane] + g_uv[(size_t)(BQ + p) * 32 + lane] + b1[lane], 0.f);
    // layer 2 via shfl + smem w2T
    float acc3 = b2[lane];
#pragma unroll
    for (int m = 0; m < 32; m++)
        acc3 += __shfl_sync(0xffffffffu, h2v, m) * sw2[m * 32 + lane];
    float h3v = fmaxf(acc3, 0.f);
    float hj[32];
#pragma unroll
    for (int m = 0; m < 32; m++) hj[m] = __shfl_sync(0xffffffffu, h3v, m);

    const unsigned* pm = g_mask + (size_t)(BQ + p) * NW;
    float s = 0.f;
    int cnt = 0;
    for (int w8 = 0; w8 < 8; w8++) {
        int wi = w8 * 32 + lane;
        unsigned m = qm[wi] & pm[wi];
        cnt += __popc(m);
        while (m) {
            int b = __ffs(m) - 1;
            m &= m - 1;
            int c = wi * 32 + b;
            const uint4* r4 = (const uint4*)(g_w3h + (size_t)c * 32);
            float wv = 0.f;
#pragma unroll
            for (int q4 = 0; q4 < 2; q4++) {
                uint4 v = r4[q4];
                unsigned ww[4] = {v.x, v.y, v.z, v.w};
#pragma unroll
                for (int k2 = 0; k2 < 4; k2++) {
                    float2 f = __half22float2(*(const __half2*)&ww[k2]);
                    int idx = q4 * 8 + k2 * 2;
                    wv += hj[idx] * f.x + hj[idx + 1] * f.y;
                }
            }
            s += (wv >= 0.f) ? wv : wv * 0.125f;
        }
    }
#pragma unroll
    for (int off = 16; off; off >>= 1) {
        s += __shfl_down_sync(0xffffffffu, s, off);
        cnt += __shfl_down_sync(0xffffffffu, cnt, off);
    }
    if (lane == 0) g_desc[q * 256 + p] = ((float)cnt + s) / qbits;
}

// ================= normalization + geo fusion =================
__global__ void k_final(const float* __restrict__ qloc, const float* __restrict__ ploc,
                        const float* __restrict__ pa, const float* __restrict__ pb,
                        const float* __restrict__ pc, const float* __restrict__ pd,
                        float* __restrict__ out) {
    __shared__ float red[256];
    int q = blockIdx.x, p = threadIdx.x;
    float ds = g_desc[q * 256 + p];
    red[p] = ds;
    __syncthreads();
    for (int s = 128; s > 0; s >>= 1) {
        if (p < s) red[p] += red[p + s];
        __syncthreads();
    }
    float mean = red[0] / 256.f;
    __syncthreads();
    float df = ds - mean;
    red[p] = df * df;
    __syncthreads();
    for (int s = 128; s > 0; s >>= 1) {
        if (p < s) red[p] += red[p + s];
        __syncthreads();
    }
    float stddev = sqrtf(red[0] / 255.f);
    float dsn = df / (stddev + 1e-6f);
    float dx = qloc[q * 2] - ploc[p * 2];
    float dy = qloc[q * 2 + 1] - ploc[p * 2 + 1];
    float dist = sqrtf(dx * dx + dy * dy);
    float A = *pa, B = *pb, Cc2 = *pc, D = *pd;
    float sig = 1.f / (1.f + expf(-(A * dsn + B)));
    out[q * 256 + p] = (Cc2 - sig) * (-logf(dist + 1.f) - D);
}

// ================= launch =================
extern "C" void kernel_launch(void* const* d_in, const int* in_sizes, int n_in,
                              void* d_out, int out_size) {
    const float* query_x  = (const float*)d_in[0];
    const float* query_loc = (const float*)d_in[1];
    const float* poi_x    = (const float*)d_in[2];
    const float* poi_loc  = (const float*)d_in[3];
    const float* enc_w    = (const float*)d_in[4];
    const float* cw1 = (const float*)d_in[5];  const float* cb1 = (const float*)d_in[6];
    const float* cw2 = (const float*)d_in[7];  const float* cb2 = (const float*)d_in[8];
    const float* cw3 = (const float*)d_in[9];  const float* cb3 = (const float*)d_in[10];
    const float* dw1 = (const float*)d_in[11]; const float* db1 = (const float*)d_in[12];
    const float* dw2 = (const float*)d_in[13]; const float* db2 = (const float*)d_in[14];
    const float* dw3 = (const float*)d_in[15];
    const float* pa = (const float*)d_in[16];
    const float* pb = (const float*)d_in[17];
    const float* pc = (const float*)d_in[18];
    const float* pd = (const float*)d_in[19];
    float* out = (float*)d_out;

    float *p_out3;
    __half *p_wH, *p_hAH, *p_hBH;
    cudaGetSymbolAddress((void**)&p_wH, g_wH);
    cudaGetSymbolAddress((void**)&p_hAH, g_hAH);
    cudaGetSymbolAddress((void**)&p_hBH, g_hBH);
    cudaGetSymbolAddress((void**)&p_out3, g_out3);

    cudaFuncSetAttribute(k_conv_mma, cudaFuncAttributeMaxDynamicSharedMemorySize, CONV_SMEM);

    // fused prep
    k_prep<<<ZA + ZB + ZC, 256>>>(dw1, dw2, cw1, cw2, cw3, enc_w, dw3);
    // encode + blooms (coalesced, fp16 encT)
    k_encode<<<dim3(NB, L), 256>>>(query_x, poi_x);
    // conv stack: pure fp16 (Ah*Wh), 512-thr CTAs, K64, 3-stage ring
    dim3 cgrid(NB * L / 64, 2);
    k_conv_mma<<<cgrid, 512, CONV_SMEM>>>(p_hAH, p_wH, cb1, p_hBH, (float*)0);
    k_conv_mma<<<cgrid, 512, CONV_SMEM>>>(p_hBH, p_wH + H1 * KTOT, cb2, p_hAH, (float*)0);
    k_conv_mma<<<cgrid, 512, CONV_SMEM>>>(p_hAH, p_wH + 2 * H1 * KTOT, cb3, (__half*)0, p_out3);
    // tail: emb + factored layer-1 partials, fused pairwise decode, final
    k_emb<<<NB, 256>>>();
    k_fused<<<dim3(32, 32), 256>>>(db1, db2);
    k_final<<<BQ, 256>>>(query_loc, poi_loc, pa, pb, pc, pd, out);
}